// round 3
// baseline (speedup 1.0000x reference)
#include <cuda_runtime.h>
#include <cstdint>

#define N_NODES 100000
#define N_EDGES 3200000
#define IN_CH   500
#define HID     64
#define OUT_CH  40
#define K_HOPS  10

// ---------------- scratch (device globals: no runtime allocation) ----------------
__device__ int   g_deg[N_NODES];          // degree incl. self loop
__device__ int   g_fill[N_NODES];         // fill cursors for counting sort
__device__ int   g_rowptr[N_NODES + 1];   // CSR row pointers (edges only, no self loops)
__device__ float g_dinv[N_NODES];         // deg^{-1/2}
__device__ int   g_col[N_EDGES];          // CSR col (src) as int32
__device__ float g_w[N_EDGES];            // dinv[src] per CSR slot
__device__ float g_cur[N_NODES * OUT_CH]; // also holds z initially
__device__ float g_next[N_NODES * OUT_CH];
__device__ float g_hidden[N_NODES * OUT_CH];
__device__ int   g_bsum[128];             // scan block sums

__device__ __forceinline__ int clamp_node(int v) {
    return v < 0 ? 0 : (v >= N_NODES ? N_NODES - 1 : v);
}

// ---------------- stem: z = relu(BN(x@W1^T + b1)) @ W2^T + b2 ----------------
__global__ void stem_kernel(const float* __restrict__ x, const float* __restrict__ W1,
                            const float* __restrict__ b1, const float* __restrict__ W2,
                            const float* __restrict__ b2, const float* __restrict__ gamma,
                            const float* __restrict__ beta, const float* __restrict__ mean,
                            const float* __restrict__ var) {
    __shared__ float As[64][33];    // x tile [node][k]
    __shared__ float Bs[32][65];    // W1 tile transposed [k][hid]
    __shared__ float hs[64][65];    // post-relu hidden tile
    __shared__ float W2s[OUT_CH][65];
    __shared__ float Ac[HID], Bc[HID], b2s[OUT_CH];

    const int t = threadIdx.x;          // 256 threads
    const int node0 = blockIdx.x * 64;
    const int tx = t & 15, ty = t >> 4;

    if (t < HID) {
        float A = gamma[t] * rsqrtf(var[t] + 1e-5f);
        Ac[t] = A;
        Bc[t] = (b1[t] - mean[t]) * A + beta[t];
    }
    if (t < OUT_CH) b2s[t] = b2[t];

    float acc[4][4];
#pragma unroll
    for (int r = 0; r < 4; r++)
#pragma unroll
        for (int c = 0; c < 4; c++) acc[r][c] = 0.f;

    for (int kk = 0; kk < IN_CH; kk += 32) {
#pragma unroll
        for (int i = 0; i < 8; i++) {
            int idx = t + i * 256;
            int r = idx >> 5, c = idx & 31;
            int n = node0 + r, kcol = kk + c;
            As[r][c] = (n < N_NODES && kcol < IN_CH) ? x[(size_t)n * IN_CH + kcol] : 0.f;
        }
#pragma unroll
        for (int i = 0; i < 8; i++) {
            int idx = t + i * 256;
            int h = idx >> 5, c = idx & 31;
            int kcol = kk + c;
            Bs[c][h] = (kcol < IN_CH) ? W1[(size_t)h * IN_CH + kcol] : 0.f;
        }
        __syncthreads();
#pragma unroll
        for (int kq = 0; kq < 32; kq++) {
            float a[4], b[4];
#pragma unroll
            for (int r = 0; r < 4; r++) a[r] = As[ty * 4 + r][kq];
#pragma unroll
            for (int c = 0; c < 4; c++) b[c] = Bs[kq][tx * 4 + c];
#pragma unroll
            for (int r = 0; r < 4; r++)
#pragma unroll
                for (int c = 0; c < 4; c++) acc[r][c] += a[r] * b[c];
        }
        __syncthreads();
    }
#pragma unroll
    for (int r = 0; r < 4; r++)
#pragma unroll
        for (int c = 0; c < 4; c++) {
            int hd = tx * 4 + c;
            float v = acc[r][c] * Ac[hd] + Bc[hd];
            hs[ty * 4 + r][hd] = fmaxf(v, 0.f);
        }
    for (int idx = t; idx < OUT_CH * HID; idx += 256) W2s[idx >> 6][idx & 63] = W2[idx];
    __syncthreads();

    const int n = t >> 2, ob = (t & 3) * 10;
    float outv[10];
#pragma unroll
    for (int j = 0; j < 10; j++) outv[j] = b2s[ob + j];
#pragma unroll 8
    for (int c = 0; c < HID; c++) {
        float hv = hs[n][c];
#pragma unroll
        for (int j = 0; j < 10; j++) outv[j] += hv * W2s[ob + j][c];
    }
    int gn = node0 + n;
    if (gn < N_NODES) {
#pragma unroll
        for (int j = 0; j < 10; j++) g_cur[(size_t)gn * OUT_CH + ob + j] = outv[j];
    }
}

// ---------------- CSR build (edge_index is int32: JAX x64-disabled) ----------------
__global__ void zero_kernel() {
    int i = blockIdx.x * blockDim.x + threadIdx.x;
    if (i < N_NODES) { g_deg[i] = 1; g_fill[i] = 0; }  // 1 = self loop
}

__global__ void hist_kernel(const int* __restrict__ dst) {
    int e = blockIdx.x * blockDim.x + threadIdx.x;
    if (e < N_EDGES) atomicAdd(&g_deg[clamp_node(dst[e])], 1);
}

__device__ __forceinline__ int block_incl_scan(int v, int* warpSums) {
    int lane = threadIdx.x & 31, wid = threadIdx.x >> 5;
#pragma unroll
    for (int o = 1; o < 32; o <<= 1) {
        int nv = __shfl_up_sync(0xFFFFFFFFu, v, o);
        if (lane >= o) v += nv;
    }
    if (lane == 31) warpSums[wid] = v;
    __syncthreads();
    if (wid == 0) {
        int s = (lane < (int)(blockDim.x >> 5)) ? warpSums[lane] : 0;
#pragma unroll
        for (int o = 1; o < 32; o <<= 1) {
            int nv = __shfl_up_sync(0xFFFFFFFFu, s, o);
            if (lane >= o) s += nv;
        }
        warpSums[lane] = s;
    }
    __syncthreads();
    if (wid > 0) v += warpSums[wid - 1];
    return v;
}

__global__ void scan1_kernel() {
    __shared__ int ws[32];
    int i = blockIdx.x * 1024 + threadIdx.x;
    int v = (i < N_NODES) ? (g_deg[i] - 1) : 0;  // edge-only counts
    int incl = block_incl_scan(v, ws);
    if (i < N_NODES) g_rowptr[i] = incl - v;
    if (threadIdx.x == 1023) g_bsum[blockIdx.x] = incl;
}

__global__ void scan2_kernel(int nb) {
    __shared__ int s[128];
    int i = threadIdx.x;
    int v = (i < nb) ? g_bsum[i] : 0;
    s[i] = v;
    __syncthreads();
    for (int o = 1; o < 128; o <<= 1) {
        int t2 = (i >= o) ? s[i - o] : 0;
        __syncthreads();
        s[i] += t2;
        __syncthreads();
    }
    g_bsum[i] = s[i] - v;  // exclusive
}

__global__ void scan3_kernel() {
    int i = blockIdx.x * blockDim.x + threadIdx.x;
    if (i < N_NODES) {
        g_rowptr[i] += g_bsum[i >> 10];
        g_dinv[i] = rsqrtf((float)g_deg[i]);
    }
    if (i == 0) g_rowptr[N_NODES] = N_EDGES;
}

__global__ void fill_kernel(const int* __restrict__ src, const int* __restrict__ dst) {
    int e = blockIdx.x * blockDim.x + threadIdx.x;
    if (e < N_EDGES) {
        int s = clamp_node(src[e]);
        int d = clamp_node(dst[e]);
        int p = g_rowptr[d] + atomicAdd(&g_fill[d], 1);
        if (p >= 0 && p < N_EDGES) {
            g_col[p] = s;
            g_w[p] = g_dinv[s];
        }
    }
}

// ---------------- propagation: one warp per dst node ----------------
template <bool FIRST, bool LAST>
__global__ void prop_kernel(float* __restrict__ out, const float* __restrict__ temp, int k) {
    const float* cur = (k & 1) ? g_next : g_cur;
    float* next = (k & 1) ? g_cur : g_next;
    int warp = (blockIdx.x * blockDim.x + threadIdx.x) >> 5;
    int lane = threadIdx.x & 31;
    if (warp >= N_NODES) return;
    const int i = warp;
    const int start = g_rowptr[i], end = g_rowptr[i + 1];
    const float di = g_dinv[i];
    const float* crow = cur + (size_t)i * OUT_CH;
    const float c0 = crow[lane];
    const float c1 = (lane < 8) ? crow[32 + lane] : 0.f;
    float acc0 = di * c0;  // self loop (norm = di*di, outer di applied below)
    float acc1 = di * c1;
#pragma unroll 4
    for (int e = start; e < end; e++) {
        int s = g_col[e];
        float wv = g_w[e];
        const float* srow = cur + (size_t)s * OUT_CH;
        acc0 += wv * srow[lane];
        if (lane < 8) acc1 += wv * srow[32 + lane];
    }
    const float nv0 = di * acc0;
    const float nv1 = di * acc1;
    const float tk = temp[k + 1];
    float h0, h1;
    if (FIRST) {
        float t0 = temp[0];
        h0 = t0 * c0 + tk * nv0;
        h1 = t0 * c1 + tk * nv1;
    } else {
        h0 = g_hidden[(size_t)i * OUT_CH + lane] + tk * nv0;
        h1 = ((lane < 8) ? g_hidden[(size_t)i * OUT_CH + 32 + lane] : 0.f) + tk * nv1;
    }
    if (!LAST) {
        next[(size_t)i * OUT_CH + lane] = nv0;
        g_hidden[(size_t)i * OUT_CH + lane] = h0;
        if (lane < 8) {
            next[(size_t)i * OUT_CH + 32 + lane] = nv1;
            g_hidden[(size_t)i * OUT_CH + 32 + lane] = h1;
        }
    } else {
        float m = h0;
        if (lane < 8) m = fmaxf(m, h1);
#pragma unroll
        for (int o = 16; o; o >>= 1) m = fmaxf(m, __shfl_xor_sync(0xFFFFFFFFu, m, o));
        float s = expf(h0 - m) + ((lane < 8) ? expf(h1 - m) : 0.f);
#pragma unroll
        for (int o = 16; o; o >>= 1) s += __shfl_xor_sync(0xFFFFFFFFu, s, o);
        float lse = m + logf(s);
        out[(size_t)i * OUT_CH + lane] = h0 - lse;
        if (lane < 8) out[(size_t)i * OUT_CH + 32 + lane] = h1 - lse;
    }
}

// ---------------- launch: kernel launches ONLY (graph-capture safe) ----------------
extern "C" void kernel_launch(void* const* d_in, const int* in_sizes, int n_in,
                              void* d_out, int out_size) {
    const float* x    = (const float*)d_in[0];
    const int*   ei   = (const int*)d_in[1];  // [2, N_EDGES] int32 (JAX x64 disabled)
    const float* W1   = (const float*)d_in[2];
    const float* b1   = (const float*)d_in[3];
    const float* W2   = (const float*)d_in[4];
    const float* b2   = (const float*)d_in[5];
    const float* gam  = (const float*)d_in[6];
    const float* bet  = (const float*)d_in[7];
    const float* mea  = (const float*)d_in[8];
    const float* var  = (const float*)d_in[9];
    const float* temp = (const float*)d_in[10];
    float* out = (float*)d_out;
    const int* srcp = ei;
    const int* dstp = ei + N_EDGES;

    stem_kernel<<<(N_NODES + 63) / 64, 256>>>(x, W1, b1, W2, b2, gam, bet, mea, var);

    zero_kernel<<<(N_NODES + 255) / 256, 256>>>();
    hist_kernel<<<(N_EDGES + 255) / 256, 256>>>(dstp);
    const int nb = (N_NODES + 1023) / 1024;  // 98
    scan1_kernel<<<nb, 1024>>>();
    scan2_kernel<<<1, 128>>>(nb);
    scan3_kernel<<<(N_NODES + 255) / 256, 256>>>();
    fill_kernel<<<(N_EDGES + 255) / 256, 256>>>(srcp, dstp);

    const int pgrid = (N_NODES * 32 + 255) / 256;
    prop_kernel<true, false><<<pgrid, 256>>>(nullptr, temp, 0);
    for (int k = 1; k < K_HOPS - 1; k++)
        prop_kernel<false, false><<<pgrid, 256>>>(nullptr, temp, k);
    prop_kernel<false, true><<<pgrid, 256>>>(out, temp, K_HOPS - 1);
}